// round 5
// baseline (speedup 1.0000x reference)
#include <cuda_runtime.h>
#include <cstdint>

#define B_ 8
#define C_ 64
#define H_ 256
#define W_ 256
#define HW_ (H_ * W_)
#define TH 2                  // output rows per block
#define ROWS (TH + 2)         // staged input rows (with halo)
#define NS 4                  // pipeline depth (ring buffers)
#define RSTRIDE 264           // floats per smem row (idx3 = left guard, 4..259 data, 260 = right guard)

__device__ __forceinline__ void cp16(uint32_t dst, const float* src) {
    asm volatile("cp.async.cg.shared.global [%0], [%1], 16;" :: "r"(dst), "l"(src));
}
__device__ __forceinline__ void cp_commit() {
    asm volatile("cp.async.commit_group;");
}
__device__ __forceinline__ void cp_wait3() {
    asm volatile("cp.async.wait_group 3;");
}

__global__ __launch_bounds__(256, 6)
void conv_attn_pipe2(const float* __restrict__ q, const float* __restrict__ k,
                     const float* __restrict__ v, float* __restrict__ out)
{
    __shared__ __align__(16) float ring[NS][ROWS][RSTRIDE];

    const int tid = threadIdx.x;
    const int x   = tid & 127;         // 128 groups of 2 px
    const int y   = tid >> 7;          // output row within tile: 0..1
    const int w0  = x * 2;
    const int h0  = blockIdx.x * TH;
    const int b   = blockIdx.y;

    const size_t cb = (size_t)b * C_ * HW_;
    const float* qb = q + cb;
    const float* kb = k + cb;
    const float* vb = v + cb;
    float*       ob = out + cb;
    const int rowoff = (h0 + y) * W_ + w0;

    // zero the guard cells once (never overwritten by staging)
    if (tid < NS * ROWS) {
        ring[tid / ROWS][tid % ROWS][3]   = 0.0f;
        ring[tid / ROWS][tid % ROWS][260] = 0.0f;
    }

    const uint32_t ring_s = (uint32_t)__cvta_generic_to_shared(&ring[0][0][0]);

    // stage channel c of tensor base `srcb` into ring[c % NS]; 256 slots, 1/thread
    auto stage = [&](const float* srcb, int c) {
        const int      bi   = c & (NS - 1);
        const uint32_t bufb = ring_s + (uint32_t)bi * (ROWS * RSTRIDE * 4);
        const float*   chan = srcb + (size_t)c * HW_;
        const int r   = tid >> 6;             // 0..3
        const int col = (tid & 63) * 4;       // 0..252
        const int hh  = h0 - 1 + r;
        if (hh >= 0 && hh < H_) {
            cp16(bufb + (uint32_t)(r * RSTRIDE + 4 + col) * 4, chan + hh * W_ + col);
        } else {
            float4 z = make_float4(0.f, 0.f, 0.f, 0.f);
            *reinterpret_cast<float4*>(&ring[bi][r][4 + col]) = z;
        }
    };

    float s[2][9];
#pragma unroll
    for (int j = 0; j < 2; j++)
#pragma unroll
        for (int i = 0; i < 9; i++) s[j][i] = 0.0f;

    // ================= Pass 1: scores =================
    for (int c = 0; c < 3; c++) { stage(kb, c); cp_commit(); }
    float2 qcur = *reinterpret_cast<const float2*>(qb + rowoff);

#pragma unroll 1
    for (int c = 0; c < C_; c++) {
        if (c + 3 < C_) stage(kb, c + 3);
        cp_commit();
        cp_wait3();
        __syncthreads();

        float2 qnext;
        if (c + 1 < C_)
            qnext = *reinterpret_cast<const float2*>(qb + (size_t)(c + 1) * HW_ + rowoff);

        const float qa[2] = {qcur.x, qcur.y};
        const int bi = c & (NS - 1);
#pragma unroll
        for (int dy = 0; dy < 3; dy++) {
            const float* rp = &ring[bi][y + dy][4 + w0];
            const float2 m = *reinterpret_cast<const float2*>(rp);
            const float a[4] = {rp[-1], m.x, m.y, rp[2]};
#pragma unroll
            for (int j = 0; j < 2; j++)
#pragma unroll
                for (int dx = 0; dx < 3; dx++)
                    s[j][dy * 3 + dx] = fmaf(qa[j], a[j + dx], s[j][dy * 3 + dx]);
        }
        qcur = qnext;
        __syncthreads();
    }

    // ================= Softmax over 9 taps (OOB taps = score 0, zero-pad semantics) =================
#pragma unroll
    for (int j = 0; j < 2; j++) {
        float mx = s[j][0];
#pragma unroll
        for (int i = 1; i < 9; i++) mx = fmaxf(mx, s[j][i]);
        float sum = 0.0f;
#pragma unroll
        for (int i = 0; i < 9; i++) { s[j][i] = __expf(s[j][i] - mx); sum += s[j][i]; }
        const float inv = 1.0f / sum;
#pragma unroll
        for (int i = 0; i < 9; i++) s[j][i] *= inv;
    }

    // ================= Pass 2: weighted v sum =================
    for (int c = 0; c < 3; c++) { stage(vb, c); cp_commit(); }

#pragma unroll 1
    for (int c = 0; c < C_; c++) {
        if (c + 3 < C_) stage(vb, c + 3);
        cp_commit();
        cp_wait3();
        __syncthreads();

        float acc[2] = {0.f, 0.f};
        const int bi = c & (NS - 1);
#pragma unroll
        for (int dy = 0; dy < 3; dy++) {
            const float* rp = &ring[bi][y + dy][4 + w0];
            const float2 m = *reinterpret_cast<const float2*>(rp);
            const float a[4] = {rp[-1], m.x, m.y, rp[2]};
#pragma unroll
            for (int j = 0; j < 2; j++)
#pragma unroll
                for (int dx = 0; dx < 3; dx++)
                    acc[j] = fmaf(s[j][dy * 3 + dx], a[j + dx], acc[j]);
        }

        float2 o;
        o.x = acc[0]; o.y = acc[1];
        *reinterpret_cast<float2*>(ob + (size_t)c * HW_ + rowoff) = o;
        __syncthreads();
    }
}

extern "C" void kernel_launch(void* const* d_in, const int* in_sizes, int n_in,
                              void* d_out, int out_size)
{
    const float* q = (const float*)d_in[0];
    const float* k = (const float*)d_in[1];
    const float* v = (const float*)d_in[2];
    float* out = (float*)d_out;

    dim3 block(256);
    dim3 grid(H_ / TH, B_);     // 128 x 8 = 1024 blocks
    conv_attn_pipe2<<<grid, block>>>(q, k, v, out);
}